// round 2
// baseline (speedup 1.0000x reference)
#include <cuda_runtime.h>

// Pure HBM-streaming quadratic form:
//   total = sum over pairs (l1<=l2), weight w in {1,2}:
//           w * sum_s d1[s,:] . O[s,:,:] . d2[s,:]
// Overlap tensors: 356.5 MB read once -> memory-bound.
// R2: persistent balanced grid (152 SMs x 6 CTAs), grid-stride over units,
//     12x fewer atomics, weight hoisted out of the inner loop.

#define TPB 256
#define IT  8               // float4 per thread per unit
#define NUNITS 10880        // total units (each TPB*IT float4 = 32KB)
#define GRID   (152 * 6)    // one perfectly-resident wave on GB300

// delta coefficients, concatenated by l:
//   l0: [0,2048), l1: [2048,8192), l2: [8192,18432), l3: [18432,32768)
__device__ __align__(16) float g_d[32768];

__global__ void prep_kernel(const float* __restrict__ i0, const float* __restrict__ t0,
                            const float* __restrict__ i1, const float* __restrict__ t1,
                            const float* __restrict__ i2, const float* __restrict__ t2,
                            const float* __restrict__ i3, const float* __restrict__ t3,
                            float* out) {
    int idx = blockIdx.x * blockDim.x + threadIdx.x;
    if (idx == 0) out[0] = 0.0f;
    if (idx < 2048) {
        g_d[idx] = i0[idx] - t0[idx];
    } else if (idx < 8192) {
        int j = idx - 2048;  g_d[idx] = i1[j] - t1[j];
    } else if (idx < 18432) {
        int j = idx - 8192;  g_d[idx] = i2[j] - t2[j];
    } else if (idx < 32768) {
        int j = idx - 18432; g_d[idx] = i3[j] - t3[j];
    }
}

struct OvlpPtrs { const float4* p[10]; };

// One unit of one pair. D1/D2 compile-time -> div/mod become mul-shift.
// lu = local unit index within this pair's range. Returns unweighted partial.
template <int D1, int D2, int OFF1, int OFF2>
__device__ __forceinline__ float unit_acc(const float4* __restrict__ o, int lu, int tid) {
    constexpr unsigned C4 = D2 / 4;  // float4 columns; >= 64 so a warp shares one row r
    float acc = 0.0f;
    unsigned base = (unsigned)lu * (TPB * IT) + tid;
#pragma unroll
    for (int it = 0; it < IT; ++it) {
        unsigned idx4 = base + (unsigned)it * TPB;
        unsigned c4 = idx4 % C4;
        unsigned rs = idx4 / C4;
        unsigned r  = rs % (unsigned)D1;
        unsigned s  = rs / (unsigned)D1;
        float4 ov = __ldcs(&o[idx4]);                                   // streamed, evict-first
        const float4 d2 = *(const float4*)&g_d[OFF2 + s * D2 + c4 * 4]; // L1/L2-resident
        float d1 = g_d[OFF1 + s * D1 + r];                              // warp-uniform broadcast
        acc = fmaf(d1, ov.x * d2.x + ov.y * d2.y + ov.z * d2.z + ov.w * d2.w, acc);
    }
    return acc;
}

// Unit-count prefix sums per pair (each unit = TPB*IT float4 = 8192 floats):
// (0,0):64  (0,1):192  (0,2):320  (0,3):448  (1,1):576
// (1,2):960 (1,3):1344 (2,2):1600 (2,3):2240 (3,3):3136   total = 10880
__global__ void __launch_bounds__(TPB, 6) rho_kernel(OvlpPtrs o, float* __restrict__ out) {
    int tid = threadIdx.x;
    float acc1 = 0.0f;  // weight-1 pairs (diagonal)
    float acc2 = 0.0f;  // weight-2 pairs (off-diagonal)

    for (int u = blockIdx.x; u < NUNITS; u += GRID) {
        if      (u <    64) acc1 += unit_acc< 256,  256,     0,     0>(o.p[0], u,         tid);
        else if (u <   256) acc2 += unit_acc< 256,  768,     0,  2048>(o.p[1], u -    64, tid);
        else if (u <   576) acc2 += unit_acc< 256, 1280,     0,  8192>(o.p[2], u -   256, tid);
        else if (u <  1024) acc2 += unit_acc< 256, 1792,     0, 18432>(o.p[3], u -   576, tid);
        else if (u <  1600) acc1 += unit_acc< 768,  768,  2048,  2048>(o.p[4], u -  1024, tid);
        else if (u <  2560) acc2 += unit_acc< 768, 1280,  2048,  8192>(o.p[5], u -  1600, tid);
        else if (u <  3904) acc2 += unit_acc< 768, 1792,  2048, 18432>(o.p[6], u -  2560, tid);
        else if (u <  5504) acc1 += unit_acc<1280, 1280,  8192,  8192>(o.p[7], u -  3904, tid);
        else if (u <  7744) acc2 += unit_acc<1280, 1792,  8192, 18432>(o.p[8], u -  5504, tid);
        else                acc1 += unit_acc<1792, 1792, 18432, 18432>(o.p[9], u -  7744, tid);
    }

    float acc = fmaf(2.0f, acc2, acc1);

    // warp reduce
#pragma unroll
    for (int off = 16; off > 0; off >>= 1)
        acc += __shfl_down_sync(0xffffffffu, acc, off);

    __shared__ float ws[TPB / 32];
    if ((tid & 31) == 0) ws[tid >> 5] = acc;
    __syncthreads();
    if (tid == 0) {
        float s = ws[0];
#pragma unroll
        for (int w = 1; w < TPB / 32; ++w) s += ws[w];
        atomicAdd(out, s);
    }
}

extern "C" void kernel_launch(void* const* d_in, const int* in_sizes, int n_in,
                              void* d_out, int out_size) {
    (void)in_sizes; (void)n_in; (void)out_size;
    const float* i0 = (const float*)d_in[0];
    const float* t0 = (const float*)d_in[1];
    const float* i1 = (const float*)d_in[2];
    const float* t1 = (const float*)d_in[3];
    const float* i2 = (const float*)d_in[4];
    const float* t2 = (const float*)d_in[5];
    const float* i3 = (const float*)d_in[6];
    const float* t3 = (const float*)d_in[7];

    OvlpPtrs o;
    for (int k = 0; k < 10; ++k) o.p[k] = (const float4*)d_in[8 + k];

    float* out = (float*)d_out;
    prep_kernel<<<128, TPB>>>(i0, t0, i1, t1, i2, t2, i3, t3, out);
    rho_kernel<<<GRID, TPB>>>(o, out);
}

// round 3
// speedup vs baseline: 1.1393x; 1.1393x over previous
#include <cuda_runtime.h>

// Pure HBM-streaming quadratic form:
//   total = sum over pairs (l1<=l2), weight w in {1,2}:
//           w * sum_s d1[s,:] . O[s,:,:] . d2[s,:]
// Overlap tensors: 356.5 MB read once -> memory-bound.
// R3: back to one-unit-per-block (R1 scheme; HW work-stealing beats static
//     partition), but IT=4 + __launch_bounds__(256,8) -> 32 regs, 8 CTAs/SM,
//     100% occupancy for better DRAM latency hiding.

#define TPB 256
#define IT  4                 // float4 per thread; unit = TPB*IT*4 = 4096 floats
#define NUNITS 21760          // total blocks

// delta coefficients, concatenated by l:
//   l0: [0,2048), l1: [2048,8192), l2: [8192,18432), l3: [18432,32768)
__device__ __align__(16) float g_d[32768];

__global__ void prep_kernel(const float* __restrict__ i0, const float* __restrict__ t0,
                            const float* __restrict__ i1, const float* __restrict__ t1,
                            const float* __restrict__ i2, const float* __restrict__ t2,
                            const float* __restrict__ i3, const float* __restrict__ t3,
                            float* out) {
    int idx = blockIdx.x * blockDim.x + threadIdx.x;
    if (idx == 0) out[0] = 0.0f;
    if (idx < 2048) {
        g_d[idx] = i0[idx] - t0[idx];
    } else if (idx < 8192) {
        int j = idx - 2048;  g_d[idx] = i1[j] - t1[j];
    } else if (idx < 18432) {
        int j = idx - 8192;  g_d[idx] = i2[j] - t2[j];
    } else if (idx < 32768) {
        int j = idx - 18432; g_d[idx] = i3[j] - t3[j];
    }
}

struct OvlpPtrs { const float4* p[10]; };

// One unit of one pair. D1/D2 compile-time -> div/mod become mul-shift.
// lu = local unit index within this pair's range.
template <int D1, int D2, int W, int OFF1, int OFF2>
__device__ __forceinline__ float unit_acc(const float4* __restrict__ o, int lu, int tid) {
    constexpr unsigned C4 = D2 / 4;  // float4 columns; >= 64 so a warp shares one row r
    float acc = 0.0f;
    unsigned base = (unsigned)lu * (TPB * IT) + tid;
#pragma unroll
    for (int it = 0; it < IT; ++it) {
        unsigned idx4 = base + (unsigned)it * TPB;
        unsigned c4 = idx4 % C4;
        unsigned rs = idx4 / C4;
        unsigned r  = rs % (unsigned)D1;
        unsigned s  = rs / (unsigned)D1;
        float4 ov = __ldcs(&o[idx4]);                                   // streamed, evict-first
        const float4 d2 = *(const float4*)&g_d[OFF2 + s * D2 + c4 * 4]; // L1/L2-resident
        float d1 = g_d[OFF1 + s * D1 + r] * (float)W;                   // warp-uniform broadcast
        acc = fmaf(d1, ov.x * d2.x + ov.y * d2.y + ov.z * d2.z + ov.w * d2.w, acc);
    }
    return acc;
}

// Unit-count prefix sums per pair (each unit = TPB*IT float4 = 4096 floats):
// (0,0):128  (0,1):384  (0,2):640  (0,3):896  (1,1):1152
// (1,2):1920 (1,3):2688 (2,2):3200 (2,3):4480 (3,3):6272  total = 21760
__global__ void __launch_bounds__(TPB, 8) rho_kernel(OvlpPtrs o, float* __restrict__ out) {
    int b = blockIdx.x;
    int tid = threadIdx.x;
    float acc;
    if      (b <   128) acc = unit_acc< 256,  256, 1,     0,     0>(o.p[0], b,         tid);
    else if (b <   512) acc = unit_acc< 256,  768, 2,     0,  2048>(o.p[1], b -   128, tid);
    else if (b <  1152) acc = unit_acc< 256, 1280, 2,     0,  8192>(o.p[2], b -   512, tid);
    else if (b <  2048) acc = unit_acc< 256, 1792, 2,     0, 18432>(o.p[3], b -  1152, tid);
    else if (b <  3200) acc = unit_acc< 768,  768, 1,  2048,  2048>(o.p[4], b -  2048, tid);
    else if (b <  5120) acc = unit_acc< 768, 1280, 2,  2048,  8192>(o.p[5], b -  3200, tid);
    else if (b <  7808) acc = unit_acc< 768, 1792, 2,  2048, 18432>(o.p[6], b -  5120, tid);
    else if (b < 11008) acc = unit_acc<1280, 1280, 1,  8192,  8192>(o.p[7], b -  7808, tid);
    else if (b < 15488) acc = unit_acc<1280, 1792, 2,  8192, 18432>(o.p[8], b - 11008, tid);
    else                acc = unit_acc<1792, 1792, 1, 18432, 18432>(o.p[9], b - 15488, tid);

    // warp reduce
#pragma unroll
    for (int off = 16; off > 0; off >>= 1)
        acc += __shfl_down_sync(0xffffffffu, acc, off);

    __shared__ float ws[TPB / 32];
    if ((tid & 31) == 0) ws[tid >> 5] = acc;
    __syncthreads();
    if (tid == 0) {
        float s = ws[0];
#pragma unroll
        for (int w = 1; w < TPB / 32; ++w) s += ws[w];
        atomicAdd(out, s);
    }
}

extern "C" void kernel_launch(void* const* d_in, const int* in_sizes, int n_in,
                              void* d_out, int out_size) {
    (void)in_sizes; (void)n_in; (void)out_size;
    const float* i0 = (const float*)d_in[0];
    const float* t0 = (const float*)d_in[1];
    const float* i1 = (const float*)d_in[2];
    const float* t1 = (const float*)d_in[3];
    const float* i2 = (const float*)d_in[4];
    const float* t2 = (const float*)d_in[5];
    const float* i3 = (const float*)d_in[6];
    const float* t3 = (const float*)d_in[7];

    OvlpPtrs o;
    for (int k = 0; k < 10; ++k) o.p[k] = (const float4*)d_in[8 + k];

    float* out = (float*)d_out;
    prep_kernel<<<128, TPB>>>(i0, t0, i1, t1, i2, t2, i3, t3, out);
    rho_kernel<<<NUNITS, TPB>>>(o, out);
}